// round 11
// baseline (speedup 1.0000x reference)
#include <cuda_runtime.h>
#include <math.h>

typedef unsigned long long u64;

#define NT 512

// padded phys layout (verified per half-warp for all four round maps)
__device__ __forceinline__ int PH(int i) { return i + (i >> 3); }

// forward CNOT-ring parity masks: bit_b(P(j)) = parity(j & PM_b)
#define PM11 0x7FF
#define PM10 0xC00
#define PM9  0xE00
#define PM8  0xF00
#define PM7  0xF80
#define PM6  0xFC0
#define PM5  0xFE0
#define PM4  0xFF0
#define PM3  0xFF8
#define PM2  0xFFC
#define PM1  0xFFE
#define PM0  0xFFF

__device__ __forceinline__ float2 cmul(float2 a, float2 b) {
    return make_float2(a.x * b.x - a.y * b.y, a.x * b.y + a.y * b.x);
}
__device__ __forceinline__ u64 pack2(float x, float y) {
    u64 r; asm("mov.b64 %0, {%1, %2};" : "=l"(r) : "f"(x), "f"(y)); return r;
}
__device__ __forceinline__ float2 unpack2(u64 v) {
    float2 r; asm("mov.b64 {%0, %1}, %2;" : "=f"(r.x), "=f"(r.y) : "l"(v)); return r;
}
__device__ __forceinline__ u64 swp(u64 v) {
    float2 t = unpack2(v); return pack2(t.y, t.x);
}
__device__ __forceinline__ u64 ffma2(u64 a, u64 b, u64 c) {
    u64 d; asm("fma.rn.f32x2 %0, %1, %2, %3;" : "=l"(d) : "l"(a), "l"(b), "l"(c)); return d;
}
__device__ __forceinline__ u64 fmul2(u64 a, u64 b) {
    u64 d; asm("mul.rn.f32x2 %0, %1, %2;" : "=l"(d) : "l"(a), "l"(b)); return d;
}

// inverse-perm gather for target amp (t<<3)|k, t 9-bit, k 3-bit
__device__ __forceinline__ int GATHER(int t, int k) {
    int g = (t << 2) ^ (t << 3);      // XOR of BINV[3..11] over t bits
    if (k & 1) g ^= 0xC01;            // BINV[0]
    if (k & 2) g ^= 0x003;            // BINV[1]
    if (k & 4) g ^= 0x006;            // BINV[2]
    return g;
}

// One round on 8 register amps: 4x4 stage (k bits 0,1) + 2x2 stage (k bit 2).
// Matrix entries packed {mx, mx, -my, my}; single-accumulator chains (reuse).
__device__ __forceinline__ void round8(const float4* __restrict__ MA,   // 16
                                       const float4* __restrict__ MB,   // 4
                                       u64* A) {
    {   // stage A: 2 quads c (k bit2), 4x4 over k bits 0,1
        u64 S[8];
        #pragma unroll
        for (int k = 0; k < 8; k++) S[k] = swp(A[k]);
        u64 out[8];
        #pragma unroll
        for (int e = 0; e < 4; e++) {
            float4 q0 = MA[e*4+0], q1 = MA[e*4+1], q2 = MA[e*4+2], q3 = MA[e*4+3];
            u64 r0 = pack2(q0.x, q0.y), i0 = pack2(q0.z, q0.w);
            u64 r1 = pack2(q1.x, q1.y), i1 = pack2(q1.z, q1.w);
            u64 r2 = pack2(q2.x, q2.y), i2 = pack2(q2.z, q2.w);
            u64 r3 = pack2(q3.x, q3.y), i3 = pack2(q3.z, q3.w);
            #pragma unroll
            for (int c = 0; c < 2; c++) {
                u64 o = fmul2(r0, A[4*c+0]);
                o = ffma2(i0, S[4*c+0], o);
                o = ffma2(r1, A[4*c+1], o);
                o = ffma2(i1, S[4*c+1], o);
                o = ffma2(r2, A[4*c+2], o);
                o = ffma2(i2, S[4*c+2], o);
                o = ffma2(r3, A[4*c+3], o);
                o = ffma2(i3, S[4*c+3], o);
                out[4*c+e] = o;
            }
        }
        #pragma unroll
        for (int k = 0; k < 8; k++) A[k] = out[k];
    }
    {   // stage B: 2x2 over k bit 2, pairs (A[j], A[4+j])
        float4 q0 = MB[0], q1 = MB[1], q2 = MB[2], q3 = MB[3];
        u64 g00r = pack2(q0.x, q0.y), g00i = pack2(q0.z, q0.w);
        u64 g01r = pack2(q1.x, q1.y), g01i = pack2(q1.z, q1.w);
        u64 g10r = pack2(q2.x, q2.y), g10i = pack2(q2.z, q2.w);
        u64 g11r = pack2(q3.x, q3.y), g11i = pack2(q3.z, q3.w);
        #pragma unroll
        for (int j = 0; j < 4; j++) {
            u64 a0 = A[j], a1 = A[4+j];
            u64 s0 = swp(a0), s1 = swp(a1);
            u64 o0 = fmul2(g00r, a0);
            o0 = ffma2(g00i, s0, o0);
            o0 = ffma2(g01r, a1, o0);
            o0 = ffma2(g01i, s1, o0);
            u64 o1 = fmul2(g10r, a0);
            o1 = ffma2(g10i, s0, o1);
            o1 = ffma2(g11r, a1, o1);
            o1 = ffma2(g11i, s1, o1);
            A[j] = o0; A[4+j] = o1;
        }
    }
}

// Fused: every block (one per SM) redundantly runs the 12-qubit sim + MLP,
// then broadcasts its grid-strided slice of the 64 MiB output.
__global__ __launch_bounds__(NT, 1)
void qae_fused_kernel(const float* __restrict__ w,     // (3,12,3)
                      const float* __restrict__ W1,    // (32,12)
                      const float* __restrict__ b1,    // (32,)
                      const float* __restrict__ W2,    // (16,32)
                      const float* __restrict__ b2,    // (16,)
                      float4* __restrict__ out, int n4)
{
    __shared__ u64    buf[4608];          // 4096 amps padded (36 KB)
    __shared__ float4 sM4A[8][16];        // fused 4x4 per (layer,round)
    __shared__ float4 sM2[8][4];          // 2x2 per (layer,round)
    __shared__ float2 sG[36][4];          // per (layer,qubit) fused gate
    __shared__ float2 sHi[64], sLo[64];   // layer-1 product prefix tables
    __shared__ float  sPart[16][12];
    __shared__ float  sZ[12], sH[32];
    __shared__ float4 sPix4[4];           // 16 final pixels
    __shared__ float  sW1[384], sB1[32], sW2[512], sB2[16];

    const int t = threadIdx.x;            // 0..511

    // ---- prefetch MLP weights into smem ----
    if (t < 96)
        reinterpret_cast<float4*>(sW1)[t] = reinterpret_cast<const float4*>(W1)[t];
    else if (t >= 96 && t < 128)
        sB1[t - 96] = b1[t - 96];
    else if (t < 256)
        reinterpret_cast<float4*>(sW2)[t - 128] = reinterpret_cast<const float4*>(W2)[t - 128];
    if (t < 16) sB2[t] = b2[t];

    // ---- per-(layer,qubit) 2x2 gates: M = RZ @ RY @ RX (RZ dropped layer 3) ----
    if (t < 36) {
        const float* wp = w + t * 3;
        int layer = t / 12;
        float hx = 0.5f * wp[0], hy = 0.5f * wp[1], hz = 0.5f * wp[2];
        float cx, sx, cy, sy, cz, sz;
        __sincosf(hx, &sx, &cx);
        __sincosf(hy, &sy, &cy);
        __sincosf(hz, &sz, &cz);
        float2 RX00 = make_float2(cx, 0.f), RX01 = make_float2(0.f, -sx);
        float2 RX10 = make_float2(0.f, -sx), RX11 = make_float2(cx, 0.f);
        float2 RY00 = make_float2(cy, 0.f), RY01 = make_float2(-sy, 0.f);
        float2 RY10 = make_float2(sy, 0.f), RY11 = make_float2(cy, 0.f);
        float2 t00 = cmul(RY00, RX00), t00b = cmul(RY01, RX10);
        float2 t01 = cmul(RY00, RX01), t01b = cmul(RY01, RX11);
        float2 t10 = cmul(RY10, RX00), t10b = cmul(RY11, RX10);
        float2 t11 = cmul(RY10, RX01), t11b = cmul(RY11, RX11);
        float2 A00 = make_float2(t00.x + t00b.x, t00.y + t00b.y);
        float2 A01 = make_float2(t01.x + t01b.x, t01.y + t01b.y);
        float2 A10 = make_float2(t10.x + t10b.x, t10.y + t10b.y);
        float2 A11 = make_float2(t11.x + t11b.x, t11.y + t11b.y);
        if (layer == 2) {
            sG[t][0] = A00; sG[t][1] = A01; sG[t][2] = A10; sG[t][3] = A11;
        } else {
            float2 RZ0 = make_float2(cz, -sz), RZ1 = make_float2(cz, sz);
            sG[t][0] = cmul(RZ0, A00);
            sG[t][1] = cmul(RZ0, A01);
            sG[t][2] = cmul(RZ1, A10);
            sG[t][3] = cmul(RZ1, A11);
        }
    }
    __syncthreads();

    // ---- fused 4x4 mats: s = 4*(layer-1)+r, bit pair (3r, 3r+1) ----
    if (t < 128) {
        int s = t >> 4, e = t & 15;
        int l = 1 + (s >> 2), r = s & 3;
        int qlo = 11 - 3 * r, qhi = 10 - 3 * r;   // bit 3r <-> qubit 11-3r
        int eo = e >> 2, ei = e & 3;
        float2 mh = sG[l * 12 + qhi][(eo >> 1) * 2 + (ei >> 1)];
        float2 ml = sG[l * 12 + qlo][(eo & 1) * 2 + (ei & 1)];
        float2 mm = cmul(mh, ml);
        sM4A[s][e] = make_float4(mm.x, mm.x, -mm.y, mm.y);
    } else if (t < 160) {
        // 2x2 mats: bit 3r+2 <-> qubit 9-3r
        int s = (t - 128) >> 2, e = (t - 128) & 3;
        int l = 1 + (s >> 2), r = s & 3;
        float2 mm = sG[l * 12 + (9 - 3 * r)][e];
        sM2[s][e] = make_float4(mm.x, mm.x, -mm.y, mm.y);
    } else if (t < 224) {                 // sHi: qubits 0..5 <-> bits 11..6
        int h = t - 160;
        float2 pp = make_float2(1.f, 0.f);
        #pragma unroll
        for (int q = 0; q < 6; q++) {
            int bit = (h >> (5 - q)) & 1;
            pp = cmul(pp, bit ? sG[q][2] : sG[q][0]);
        }
        sHi[h] = pp;
    } else if (t < 288) {                 // sLo: qubits 6..11 <-> bits 5..0
        int mI = t - 224;
        float2 pp = make_float2(1.f, 0.f);
        #pragma unroll
        for (int q = 6; q < 12; q++) {
            int bit = (mI >> (11 - q)) & 1;
            pp = cmul(pp, bit ? sG[q][2] : sG[q][0]);
        }
        sLo[mI] = pp;
    }
    __syncthreads();

    u64 A[8];
    // round index bases: r0: (t<<3)|k   r1: hi6|{k<<3}|lo3   r2: hi3|{k<<6}|lo6   r3: {k<<9}|t
    const int i1b = ((t >> 3) << 6) | (t & 7);
    const int i2b = ((t >> 6) << 9) | (t & 63);

    // ===== layer 2, round 0: P1-folded product gather =====
    #pragma unroll
    for (int k = 0; k < 8; k++) {
        int g = GATHER(t, k);
        float2 v = cmul(sHi[g >> 6], sLo[g & 63]);
        A[k] = pack2(v.x, v.y);
    }
    round8(sM4A[0], sM2[0], A);
    #pragma unroll
    for (int k = 0; k < 8; k++) buf[PH((t << 3) | k)] = A[k];
    __syncthreads();

    // ===== layer 2, rounds 1-3 =====
    #pragma unroll
    for (int k = 0; k < 8; k++) A[k] = buf[PH(i1b | (k << 3))];
    round8(sM4A[1], sM2[1], A);
    #pragma unroll
    for (int k = 0; k < 8; k++) buf[PH(i1b | (k << 3))] = A[k];
    __syncthreads();

    #pragma unroll
    for (int k = 0; k < 8; k++) A[k] = buf[PH(i2b | (k << 6))];
    round8(sM4A[2], sM2[2], A);
    #pragma unroll
    for (int k = 0; k < 8; k++) buf[PH(i2b | (k << 6))] = A[k];
    __syncthreads();

    #pragma unroll
    for (int k = 0; k < 8; k++) A[k] = buf[PH((k << 9) | t)];
    round8(sM4A[3], sM2[3], A);
    #pragma unroll
    for (int k = 0; k < 8; k++) buf[PH((k << 9) | t)] = A[k];
    __syncthreads();

    // ===== layer 3, round 0: P2-folded gather =====
    #pragma unroll
    for (int k = 0; k < 8; k++) A[k] = buf[PH(GATHER(t, k))];
    __syncthreads();                      // all permuted reads before overwrite
    round8(sM4A[4], sM2[4], A);
    #pragma unroll
    for (int k = 0; k < 8; k++) buf[PH((t << 3) | k)] = A[k];
    __syncthreads();

    // ===== layer 3, rounds 1-2 =====
    #pragma unroll
    for (int k = 0; k < 8; k++) A[k] = buf[PH(i1b | (k << 3))];
    round8(sM4A[5], sM2[5], A);
    #pragma unroll
    for (int k = 0; k < 8; k++) buf[PH(i1b | (k << 3))] = A[k];
    __syncthreads();

    #pragma unroll
    for (int k = 0; k < 8; k++) A[k] = buf[PH(i2b | (k << 6))];
    round8(sM4A[6], sM2[6], A);
    #pragma unroll
    for (int k = 0; k < 8; k++) buf[PH(i2b | (k << 6))] = A[k];
    __syncthreads();

    // ===== layer 3, round 3: reduce straight from registers =====
    #pragma unroll
    for (int k = 0; k < 8; k++) A[k] = buf[PH((k << 9) | t)];
    round8(sM4A[7], sM2[7], A);

    // probabilities + 3-bit Walsh-Hadamard over k (amp bits 9,10,11)
    float pr[8];
    #pragma unroll
    for (int k = 0; k < 8; k++) {
        float2 v = unpack2(A[k]);
        pr[k] = fmaf(v.x, v.x, v.y * v.y);
    }
    #pragma unroll
    for (int s = 1; s < 8; s <<= 1) {
        #pragma unroll
        for (int k = 0; k < 8; k++) {
            if (!(k & s)) {
                float u = pr[k], vv = pr[k | s];
                pr[k] = u + vv;
                pr[k | s] = u - vv;
            }
        }
    }

    // <Z_q> with P3 folded: value = WHT[(m>>9)&7], sign = popc(t & m & 0x1FF)
    float zloc[12];
    {
        const int MQ[12] = {PM11, PM10, PM9, PM8, PM7, PM6,
                            PM5,  PM4,  PM3, PM2, PM1, PM0};
        #pragma unroll
        for (int q = 0; q < 12; q++) {
            const int m = MQ[q];
            float wv = pr[(m >> 9) & 7];           // constexpr index
            zloc[q] = (__popc(t & (m & 0x1FF)) & 1) ? -wv : wv;
        }
    }
    #pragma unroll
    for (int q = 0; q < 12; q++) {
        float x = zloc[q];
        #pragma unroll
        for (int off = 16; off > 0; off >>= 1)
            x += __shfl_down_sync(0xFFFFFFFFu, x, off);
        zloc[q] = x;
    }
    int warp = t >> 5, lane = t & 31;
    if (lane == 0) {
        #pragma unroll
        for (int q = 0; q < 12; q++) sPart[warp][q] = zloc[q];
    }
    __syncthreads();
    if (t < 12) {
        float s = 0.f;
        #pragma unroll
        for (int wi = 0; wi < 16; wi++) s += sPart[wi][t];
        sZ[t] = s;
    }
    __syncthreads();

    // ---- MLP head: 12 -> 32 (ReLU) -> 16 (sigmoid), weights in smem ----
    if (t < 32) {
        float acc = sB1[t];
        #pragma unroll
        for (int k = 0; k < 12; k++) acc += sW1[t * 12 + k] * sZ[k];
        sH[t] = fmaxf(acc, 0.f);
    }
    __syncthreads();
    if (t < 16) {
        float acc = sB2[t];
        #pragma unroll
        for (int k = 0; k < 32; k++) acc += sW2[t * 32 + k] * sH[k];
        reinterpret_cast<float*>(sPix4)[t] = 1.f / (1.f + __expf(-acc));
    }
    __syncthreads();

    // ===== broadcast: grid-strided slice, 8 front-batched STG.128 =====
    const int gt = blockIdx.x * NT + t;
    const int stride = gridDim.x * NT;             // multiple of 4
    float4 v = sPix4[gt & 3];                      // constant per thread
    int i = gt;
    for (; i + 7 * stride < n4; i += 8 * stride) {
        out[i]              = v;
        out[i + stride]     = v;
        out[i + 2 * stride] = v;
        out[i + 3 * stride] = v;
        out[i + 4 * stride] = v;
        out[i + 5 * stride] = v;
        out[i + 6 * stride] = v;
        out[i + 7 * stride] = v;
    }
    for (; i < n4; i += stride) out[i] = v;
}

extern "C" void kernel_launch(void* const* d_in, const int* in_sizes, int n_in,
                              void* d_out, int out_size)
{
    // metadata order: images, qweights, W1, b1, W2, b2
    const float* w  = (const float*)d_in[1];
    const float* W1 = (const float*)d_in[2];
    const float* b1 = (const float*)d_in[3];
    const float* W2 = (const float*)d_in[4];
    const float* b2 = (const float*)d_in[5];

    int n4 = out_size / 4;                         // float4 count
    qae_fused_kernel<<<148, NT>>>(w, W1, b1, W2, b2, (float4*)d_out, n4);
}